// round 11
// baseline (speedup 1.0000x reference)
#include <cuda_runtime.h>
#include <math_constants.h>

#define N_NODES 8192
#define F 512
#define ALPHA 0.2f
#define NPART 128          // stage-1 partial blocks (4 o-rows each)
#define ATTN_GRID (148 * 4)   // persistent: 4 CTAs/SM on 148 SMs

// Scratch (no dynamic allocation allowed)
__device__ __align__(16) float g_part1[NPART * F];
__device__ __align__(16) float g_part2[NPART * F];
__device__ __align__(16) float g_w1[F];
__device__ __align__(16) float g_w2[F];
__device__ __align__(16) float g_s1[N_NODES];
__device__ __align__(16) float g_s2[N_NODES];
__device__ unsigned int g_s2max_u;   // monotone-encoded float max

// Monotone encoding: encode(x) preserves float ordering under unsigned compare.
__device__ __forceinline__ unsigned int enc_f32(float x) {
    unsigned int b = __float_as_uint(x);
    return (b & 0x80000000u) ? ~b : (b | 0x80000000u);
}
__device__ __forceinline__ float dec_f32(unsigned int u) {
    return (u & 0x80000000u) ? __uint_as_float(u & 0x7fffffffu)
                             : __uint_as_float(~u);
}

// ---------------------------------------------------------------------------
// Stage 1: partial fold of attention vector through W.
// Also resets g_s2max_u for this launch (graph-replay safe: every call).
// ---------------------------------------------------------------------------
__global__ void wvec_part_kernel(const float* __restrict__ W,
                                 const float* __restrict__ a) {
    const int b = blockIdx.x;
    const int t = threadIdx.x;            // 0..255
    if (b == 0 && t == 0) g_s2max_u = 0u; // encoded -inf sentinel (below all reals)
    const int o0 = b * 4;
    float acc1a = 0.f, acc2a = 0.f;       // for k = t
    float acc1b = 0.f, acc2b = 0.f;       // for k = t + 256
    #pragma unroll
    for (int j = 0; j < 4; j++) {
        const int o = o0 + j;
        const float a1 = a[o];
        const float a2 = a[F + o];
        const float wa = W[o * F + t];
        const float wb = W[o * F + t + 256];
        acc1a = fmaf(wa, a1, acc1a);
        acc2a = fmaf(wa, a2, acc2a);
        acc1b = fmaf(wb, a1, acc1b);
        acc2b = fmaf(wb, a2, acc2b);
    }
    g_part1[b * F + t]       = acc1a;
    g_part1[b * F + t + 256] = acc1b;
    g_part2[b * F + t]       = acc2a;
    g_part2[b * F + t + 256] = acc2b;
}

// ---------------------------------------------------------------------------
// Stage 2: reduce NPART partials per k.
// ---------------------------------------------------------------------------
__global__ void wvec_reduce_kernel() {
    const int k = blockIdx.x * 256 + threadIdx.x;   // 0..511
    float s1 = 0.f, s2 = 0.f;
    #pragma unroll 16
    for (int b = 0; b < NPART; b++) {
        s1 += g_part1[b * F + k];
        s2 += g_part2[b * F + k];
    }
    g_w1[k] = s1;
    g_w2[k] = s2;
}

// ---------------------------------------------------------------------------
// Per-node scores. One warp per node row. Also reduces the global max of s2
// (CTA-level smem reduce -> one atomicMax per CTA; max is order-invariant so
// the result is exact and deterministic).
// ---------------------------------------------------------------------------
__global__ void sdot_kernel(const float* __restrict__ nodes) {
    int warp = (blockIdx.x * blockDim.x + threadIdx.x) >> 5;
    int lane = threadIdx.x & 31;
    int wid  = threadIdx.x >> 5;
    const float4* nrow = (const float4*)(nodes + (size_t)warp * F);
    const float4* w1v  = (const float4*)g_w1;
    const float4* w2v  = (const float4*)g_w2;
    float a1 = 0.f, a2 = 0.f;
    #pragma unroll
    for (int i = 0; i < (F / 4) / 32; i++) {   // 4 iters
        int idx = lane + i * 32;
        float4 v = nrow[idx];
        float4 x = w1v[idx];
        float4 y = w2v[idx];
        a1 += v.x * x.x + v.y * x.y + v.z * x.z + v.w * x.w;
        a2 += v.x * y.x + v.y * y.y + v.z * y.z + v.w * y.w;
    }
    #pragma unroll
    for (int off = 16; off; off >>= 1) {
        a1 += __shfl_xor_sync(0xffffffffu, a1, off);
        a2 += __shfl_xor_sync(0xffffffffu, a2, off);
    }
    __shared__ float sm[8];
    if (lane == 0) {
        g_s1[warp] = a1;
        g_s2[warp] = a2;
        sm[wid] = a2;
    }
    __syncthreads();
    if (threadIdx.x == 0) {
        float m = sm[0];
        #pragma unroll
        for (int w = 1; w < 8; w++) m = fmaxf(m, sm[w]);
        atomicMax(&g_s2max_u, enc_f32(m));
    }
}

// ---------------------------------------------------------------------------
// Masked row softmax. PERSISTENT: 592 CTAs (4/SM) loop over rows stride-592.
// Per row: phase 1 = pure front-batched loads + masked leaky-relu into regs;
// phase 2 = register-only exp+sum (shift C known at row start — no max
// barrier); ONE barrier per row; phase 3 = normalize + write.
// s2 re-reads hit L1 after the first row (L1 persists within launch).
// ---------------------------------------------------------------------------
__global__ void __launch_bounds__(256, 4)
attn_kernel(const float* __restrict__ adj, float* __restrict__ out) {
    const int tid  = threadIdx.x;
    const int lane = tid & 31;
    const int wid  = tid >> 5;
    const float4* __restrict__ s2v = (const float4*)g_s2;
    const float s2max = dec_f32(g_s2max_u);
    __shared__ float sm_sum[8];

    for (int row = blockIdx.x; row < N_NODES; row += ATTN_GRID) {
        const float4* __restrict__ arow = (const float4*)(adj + (size_t)row * N_NODES);
        float4* __restrict__ orow = (float4*)(out + (size_t)row * N_NODES);

        const float s1 = g_s1[row];
        float ct = s1 + s2max;
        const float C = (ct >= 0.f) ? ct : ALPHA * ct;  // per-row shift >= row max

        float e[32];

        // Phase 1: pure loads + masked leaky-relu scores into registers.
        #pragma unroll
        for (int c = 0; c < 8; c++) {
            int idx = c * 256 + tid;          // float4 index within row
            float4 a4 = arow[idx];
            float4 s4 = s2v[idx];
            float x0 = s1 + s4.x; x0 = (x0 >= 0.f) ? x0 : ALPHA * x0;
            float x1 = s1 + s4.y; x1 = (x1 >= 0.f) ? x1 : ALPHA * x1;
            float x2 = s1 + s4.z; x2 = (x2 >= 0.f) ? x2 : ALPHA * x2;
            float x3 = s1 + s4.w; x3 = (x3 >= 0.f) ? x3 : ALPHA * x3;
            e[c * 4 + 0] = (a4.x >= 0.5f) ? x0 : -CUDART_INF_F;
            e[c * 4 + 1] = (a4.y >= 0.5f) ? x1 : -CUDART_INF_F;
            e[c * 4 + 2] = (a4.z >= 0.5f) ? x2 : -CUDART_INF_F;
            e[c * 4 + 3] = (a4.w >= 0.5f) ? x3 : -CUDART_INF_F;
        }

        // Phase 2: exponentiate (registers only), accumulate sum.
        float lsum = 0.f;
        #pragma unroll
        for (int i = 0; i < 32; i++) {
            float p = __expf(e[i] - C);      // exp(-inf) -> 0 for masked
            e[i] = p;
            lsum += p;
        }

        // Block-reduce sum (8 warps) — the ONLY barrier in the row.
        #pragma unroll
        for (int off = 16; off; off >>= 1)
            lsum += __shfl_xor_sync(0xffffffffu, lsum, off);
        if (lane == 0) sm_sum[wid] = lsum;
        __syncthreads();
        float rsum = sm_sum[0];
        #pragma unroll
        for (int w = 1; w < 8; w++) rsum += sm_sum[w];
        float inv = 1.f / rsum;
        __syncthreads();   // protect sm_sum reuse next iteration

        // Phase 3: normalize + write.
        #pragma unroll
        for (int c = 0; c < 8; c++) {
            int idx = c * 256 + tid;
            float4 o4;
            o4.x = e[c * 4 + 0] * inv;
            o4.y = e[c * 4 + 1] * inv;
            o4.z = e[c * 4 + 2] * inv;
            o4.w = e[c * 4 + 3] * inv;
            orow[idx] = o4;
        }
    }
}

// ---------------------------------------------------------------------------
extern "C" void kernel_launch(void* const* d_in, const int* in_sizes, int n_in,
                              void* d_out, int out_size) {
    const float* nodes = (const float*)d_in[0];   // [8192, 512]
    const float* adj   = (const float*)d_in[1];   // [8192, 8192]
    const float* W     = (const float*)d_in[2];   // [512, 512]
    const float* a     = (const float*)d_in[3];   // [1024]
    float* out = (float*)d_out;                   // [8192, 8192]

    wvec_part_kernel<<<NPART, 256>>>(W, a);
    wvec_reduce_kernel<<<2, 256>>>();
    sdot_kernel<<<N_NODES / 8, 256>>>(nodes);     // 8 warps/block, 1 warp/row
    attn_kernel<<<ATTN_GRID, 256>>>(adj, out);
}

// round 12
// speedup vs baseline: 1.0675x; 1.0675x over previous
#include <cuda_runtime.h>
#include <math_constants.h>

#define N_NODES 8192
#define F 512
#define ALPHA 0.2f
#define NPART 128          // stage-1 partial blocks (4 o-rows each)

// Scratch (no dynamic allocation allowed)
__device__ __align__(16) float g_part1[NPART * F];
__device__ __align__(16) float g_part2[NPART * F];
__device__ __align__(16) float g_w1[F];
__device__ __align__(16) float g_w2[F];
__device__ __align__(16) float g_s1[N_NODES];
__device__ __align__(16) float g_s2[N_NODES];
__device__ unsigned int g_s2max_u;   // monotone-encoded float max

// Monotone encoding: preserves float ordering under unsigned compare.
__device__ __forceinline__ unsigned int enc_f32(float x) {
    unsigned int b = __float_as_uint(x);
    return (b & 0x80000000u) ? ~b : (b | 0x80000000u);
}
__device__ __forceinline__ float dec_f32(unsigned int u) {
    return (u & 0x80000000u) ? __uint_as_float(u & 0x7fffffffu)
                             : __uint_as_float(~u);
}

// ---------------------------------------------------------------------------
// Stage 1: partial fold of attention vector through W.
// Also resets g_s2max_u for this launch (runs first in stream every call).
// ---------------------------------------------------------------------------
__global__ void wvec_part_kernel(const float* __restrict__ W,
                                 const float* __restrict__ a) {
    const int b = blockIdx.x;
    const int t = threadIdx.x;            // 0..255
    if (b == 0 && t == 0) g_s2max_u = 0u; // encoded sentinel below all reals
    const int o0 = b * 4;
    float acc1a = 0.f, acc2a = 0.f;       // for k = t
    float acc1b = 0.f, acc2b = 0.f;       // for k = t + 256
    #pragma unroll
    for (int j = 0; j < 4; j++) {
        const int o = o0 + j;
        const float a1 = a[o];
        const float a2 = a[F + o];
        const float wa = W[o * F + t];
        const float wb = W[o * F + t + 256];
        acc1a = fmaf(wa, a1, acc1a);
        acc2a = fmaf(wa, a2, acc2a);
        acc1b = fmaf(wb, a1, acc1b);
        acc2b = fmaf(wb, a2, acc2b);
    }
    g_part1[b * F + t]       = acc1a;
    g_part1[b * F + t + 256] = acc1b;
    g_part2[b * F + t]       = acc2a;
    g_part2[b * F + t + 256] = acc2b;
}

// ---------------------------------------------------------------------------
// Stage 2: reduce NPART partials per k. 2 CTAs x 1024 threads; 4 threads per
// k, each sums 32 partials (serial chain 32 deep instead of 256), combined
// with two shfl steps. Deterministic fixed-order arithmetic.
// ---------------------------------------------------------------------------
__global__ void wvec_reduce_kernel() {
    const int gt = blockIdx.x * 1024 + threadIdx.x;  // 0..2047
    const int k = gt >> 2;            // 0..511
    const int q = gt & 3;             // quarter of the b range
    const int b0 = q * (NPART / 4);
    float s1 = 0.f, s2 = 0.f;
    #pragma unroll 8
    for (int j = 0; j < NPART / 4; j++) {
        s1 += g_part1[(b0 + j) * F + k];
        s2 += g_part2[(b0 + j) * F + k];
    }
    // combine the 4 q-lanes (adjacent lanes within the warp)
    s1 += __shfl_xor_sync(0xffffffffu, s1, 1);
    s2 += __shfl_xor_sync(0xffffffffu, s2, 1);
    s1 += __shfl_xor_sync(0xffffffffu, s1, 2);
    s2 += __shfl_xor_sync(0xffffffffu, s2, 2);
    if (q == 0) {
        g_w1[k] = s1;
        g_w2[k] = s2;
    }
}

// ---------------------------------------------------------------------------
// Per-node scores. One warp per node row. Also folds the global max of s2
// (CTA smem reduce -> one atomicMax per CTA; max is order-invariant, so the
// result is exact and deterministic across replays).
// ---------------------------------------------------------------------------
__global__ void sdot_kernel(const float* __restrict__ nodes) {
    int warp = (blockIdx.x * blockDim.x + threadIdx.x) >> 5;
    int lane = threadIdx.x & 31;
    int wid  = threadIdx.x >> 5;
    const float4* nrow = (const float4*)(nodes + (size_t)warp * F);
    const float4* w1v  = (const float4*)g_w1;
    const float4* w2v  = (const float4*)g_w2;
    float a1 = 0.f, a2 = 0.f;
    #pragma unroll
    for (int i = 0; i < (F / 4) / 32; i++) {   // 4 iters
        int idx = lane + i * 32;
        float4 v = nrow[idx];
        float4 x = w1v[idx];
        float4 y = w2v[idx];
        a1 += v.x * x.x + v.y * x.y + v.z * x.z + v.w * x.w;
        a2 += v.x * y.x + v.y * y.y + v.z * y.z + v.w * y.w;
    }
    #pragma unroll
    for (int off = 16; off; off >>= 1) {
        a1 += __shfl_xor_sync(0xffffffffu, a1, off);
        a2 += __shfl_xor_sync(0xffffffffu, a2, off);
    }
    __shared__ float sm[8];
    if (lane == 0) {
        g_s1[warp] = a1;
        g_s2[warp] = a2;
        sm[wid] = a2;
    }
    __syncthreads();
    if (threadIdx.x == 0) {
        float m = sm[0];
        #pragma unroll
        for (int w = 1; w < 8; w++) m = fmaxf(m, sm[w]);
        atomicMax(&g_s2max_u, enc_f32(m));
    }
}

// ---------------------------------------------------------------------------
// Masked row softmax. One CTA per row; 256 threads x 32 cols each.
// Phase 1 = pure front-batched loads + masked leaky-relu into regs;
// phase 2 = register-only exp+sum with precomputed shift C (no max barrier);
// ONE barrier total; phase 3 = normalize + write. (Best measured shape.)
// ---------------------------------------------------------------------------
__global__ void __launch_bounds__(256, 4)
attn_kernel(const float* __restrict__ adj, float* __restrict__ out) {
    const int row = blockIdx.x;
    const float4* __restrict__ arow = (const float4*)(adj + (size_t)row * N_NODES);
    float4* __restrict__ orow = (float4*)(out + (size_t)row * N_NODES);
    const float4* __restrict__ s2v = (const float4*)g_s2;

    const float s1 = g_s1[row];
    float ct = s1 + dec_f32(g_s2max_u);
    const float C = (ct >= 0.f) ? ct : ALPHA * ct;   // per-row shift >= row max
    const int tid  = threadIdx.x;
    const int lane = tid & 31;
    const int wid  = tid >> 5;

    float e[32];

    // Phase 1: pure loads + masked leaky-relu scores into registers.
    #pragma unroll
    for (int c = 0; c < 8; c++) {
        int idx = c * 256 + tid;          // float4 index within row
        float4 a4 = arow[idx];
        float4 s4 = s2v[idx];
        float x0 = s1 + s4.x; x0 = (x0 >= 0.f) ? x0 : ALPHA * x0;
        float x1 = s1 + s4.y; x1 = (x1 >= 0.f) ? x1 : ALPHA * x1;
        float x2 = s1 + s4.z; x2 = (x2 >= 0.f) ? x2 : ALPHA * x2;
        float x3 = s1 + s4.w; x3 = (x3 >= 0.f) ? x3 : ALPHA * x3;
        e[c * 4 + 0] = (a4.x >= 0.5f) ? x0 : -CUDART_INF_F;
        e[c * 4 + 1] = (a4.y >= 0.5f) ? x1 : -CUDART_INF_F;
        e[c * 4 + 2] = (a4.z >= 0.5f) ? x2 : -CUDART_INF_F;
        e[c * 4 + 3] = (a4.w >= 0.5f) ? x3 : -CUDART_INF_F;
    }

    // Phase 2: exponentiate (registers only), accumulate sum.
    float lsum = 0.f;
    #pragma unroll
    for (int i = 0; i < 32; i++) {
        float p = __expf(e[i] - C);      // exp(-inf) -> 0 for masked entries
        e[i] = p;
        lsum += p;
    }

    // Block-reduce sum (8 warps) — the ONLY barrier.
    __shared__ float sm_sum[8];
    #pragma unroll
    for (int off = 16; off; off >>= 1)
        lsum += __shfl_xor_sync(0xffffffffu, lsum, off);
    if (lane == 0) sm_sum[wid] = lsum;
    __syncthreads();
    float rsum = sm_sum[0];
    #pragma unroll
    for (int w = 1; w < 8; w++) rsum += sm_sum[w];
    float inv = 1.f / rsum;

    // Phase 3: normalize + write.
    #pragma unroll
    for (int c = 0; c < 8; c++) {
        int idx = c * 256 + tid;
        float4 o4;
        o4.x = e[c * 4 + 0] * inv;
        o4.y = e[c * 4 + 1] * inv;
        o4.z = e[c * 4 + 2] * inv;
        o4.w = e[c * 4 + 3] * inv;
        orow[idx] = o4;
    }
}

// ---------------------------------------------------------------------------
extern "C" void kernel_launch(void* const* d_in, const int* in_sizes, int n_in,
                              void* d_out, int out_size) {
    const float* nodes = (const float*)d_in[0];   // [8192, 512]
    const float* adj   = (const float*)d_in[1];   // [8192, 8192]
    const float* W     = (const float*)d_in[2];   // [512, 512]
    const float* a     = (const float*)d_in[3];   // [1024]
    float* out = (float*)d_out;                   // [8192, 8192]

    wvec_part_kernel<<<NPART, 256>>>(W, a);
    wvec_reduce_kernel<<<2, 1024>>>();
    sdot_kernel<<<N_NODES / 8, 256>>>(nodes);     // 8 warps/block, 1 warp/row
    attn_kernel<<<N_NODES, 256>>>(adj, out);
}